// round 5
// baseline (speedup 1.0000x reference)
#include <cuda_runtime.h>

#define NN 50000
#define NE 600000
#define HID 128

typedef unsigned long long u64;

// ---- scratch (static device allocations; no cudaMalloc allowed) ----
__device__ int   g_ni[NE];
__device__ int   g_ei[NE];
__device__ int   g_cnt[2 * NN];       // [0,NN): node degree D; [NN,2NN): hedge degree B
__device__ int   g_offs[2 * NN + 1];  // combined exclusive offsets
__device__ int   g_csr[2 * NE];       // node rows hold edge ids; edge rows hold node ids
__device__ float g_dinv[NN];
__device__ float g_binv[NN];
__device__ float g_xw[NN * HID];
__device__ float g_m[NN * HID];
__device__ float g_h[NN * HID];
__device__ int   g_is_i32;

// ---- side stream + events for forked capture (created before harness checkpoints) ----
struct SideStream {
    cudaStream_t s;
    cudaEvent_t evStart, evGemm;
    SideStream() {
        cudaStreamCreateWithFlags(&s, cudaStreamNonBlocking);
        cudaEventCreateWithFlags(&evStart, cudaEventDisableTiming);
        cudaEventCreateWithFlags(&evGemm, cudaEventDisableTiming);
    }
};
static SideStream g_ss;

// ---- packed f32x2 helpers ----
__device__ __forceinline__ u64 ffma2(u64 a, u64 b, u64 c) {
    u64 d;
    asm("fma.rn.f32x2 %0, %1, %2, %3;" : "=l"(d) : "l"(a), "l"(b), "l"(c));
    return d;
}
__device__ __forceinline__ u64 dup2(float x) {
    u64 d;
    asm("mov.b64 %0, {%1, %1};" : "=l"(d) : "f"(x));
    return d;
}

// ---- zero counts + flag (one kernel) ----
__global__ void k_zero() {
    int i = blockIdx.x * blockDim.x + threadIdx.x;
    if (i < 2 * NN) g_cnt[i] = 0;
    if (i == 0) g_is_i32 = 0;
}

__global__ void k_detect(const long long* __restrict__ hei64) {
    int i = blockIdx.x * blockDim.x + threadIdx.x;
    if (i < 4096) {
        long long v = hei64[i];
        if (v < 0 || v >= NN) atomicExch(&g_is_i32, 1);
    }
}

// ---- index decode + degree counts (2 entries / thread) ----
__global__ void k_idx_deg(const void* __restrict__ hei) {
    int t = blockIdx.x * blockDim.x + threadIdx.x;
    int i0 = t * 2;
    if (i0 >= NE) return;
    bool i32 = (g_is_i32 != 0);
#pragma unroll
    for (int k = 0; k < 2; k++) {
        int i = i0 + k;
        if (i >= NE) break;
        int n, e;
        if (i32) {
            const int* h32 = (const int*)hei;
            n = h32[i];
            e = h32[NE + i];
        } else {
            const long long* h64 = (const long long*)hei;
            n = (int)h64[i];
            e = (int)h64[NE + i];
        }
        if (n < 0 || n >= NN) n = 0;
        if (e < 0 || e >= NN) e = 0;
        g_ni[i] = n;
        g_ei[i] = e;
        atomicAdd(&g_cnt[n], 1);
        atomicAdd(&g_cnt[NN + e], 1);
    }
}

// ---- single-block scan over g_cnt[0:2NN] -> g_offs, + inverse degrees ----
#define SONE_T 1024
__global__ __launch_bounds__(SONE_T) void k_scan_one() {
    __shared__ int sh[SONE_T];
    const int TOT = 2 * NN;
    const int per = (TOT + SONE_T - 1) / SONE_T;  // 98
    int tid = threadIdx.x;
    int beg = tid * per;
    int end = beg + per < TOT ? beg + per : TOT;
    int sum = 0;
    for (int i = beg; i < end; i++) sum += g_cnt[i];
    sh[tid] = sum;
    __syncthreads();
    for (int off = 1; off < SONE_T; off <<= 1) {
        int t = (tid >= off) ? sh[tid - off] : 0;
        __syncthreads();
        sh[tid] += t;
        __syncthreads();
    }
    int run = sh[tid] - sum;  // exclusive prefix
    for (int i = beg; i < end; i++) {
        int c = g_cnt[i];
        g_offs[i] = run;
        run += c;
        float inv = c > 0 ? 1.0f / (float)c : 0.0f;
        if (i < NN) g_dinv[i] = inv;
        else        g_binv[i - NN] = inv;
    }
    if (tid == 0) g_offs[TOT] = 2 * NE;
}

// ---- CSR fill: consumes g_cnt as cursors via atomicSub ----
__global__ void k_fill() {
    int i = blockIdx.x * blockDim.x + threadIdx.x;
    if (i >= NE) return;
    int n = g_ni[i];
    int e = g_ei[i];
    int pn = g_offs[n] + atomicSub(&g_cnt[n], 1) - 1;
    g_csr[pn] = e;
    int pe = g_offs[NN + e] + atomicSub(&g_cnt[NN + e], 1) - 1;
    g_csr[pe] = n;
}

// ---- GEMM: C[M,128] = A[M,128] @ W[128,128], packed f32x2 FMA microkernel ----
__global__ __launch_bounds__(256) void k_gemm(const float* __restrict__ A,
                                              const float* __restrict__ W,
                                              float* __restrict__ C, int M) {
    __shared__ float sAT[32][129];
    __shared__ float sW[32][128];
    int tid = threadIdx.x;
    int tx = tid & 15;
    int ty = tid >> 4;
    int rb = blockIdx.x * 128;
    int lr = tid >> 3;
    int kq = tid & 7;

    u64 acc2[8][4];
#pragma unroll
    for (int i = 0; i < 8; i++)
#pragma unroll
        for (int j = 0; j < 4; j++) acc2[i][j] = 0ull;

    for (int kk = 0; kk < 128; kk += 32) {
        __syncthreads();
#pragma unroll
        for (int t = 0; t < 4; t++) {
            int r = lr + t * 32;
            float4 v = make_float4(0.f, 0.f, 0.f, 0.f);
            if (rb + r < M)
                v = *(const float4*)(A + (size_t)(rb + r) * HID + kk + kq * 4);
            sAT[kq * 4 + 0][r] = v.x;
            sAT[kq * 4 + 1][r] = v.y;
            sAT[kq * 4 + 2][r] = v.z;
            sAT[kq * 4 + 3][r] = v.w;
        }
#pragma unroll
        for (int t = 0; t < 4; t++) {
            int i4 = tid + t * 256;
            int k = i4 >> 5, c4 = i4 & 31;
            *(float4*)(&sW[k][c4 * 4]) =
                *(const float4*)(W + (size_t)(kk + k) * HID + c4 * 4);
        }
        __syncthreads();

#pragma unroll
        for (int k = 0; k < 32; k++) {
            float a[8];
#pragma unroll
            for (int i = 0; i < 8; i++) a[i] = sAT[k][ty * 8 + i];
            float4 b0 = *(const float4*)(&sW[k][tx * 8]);
            float4 b1 = *(const float4*)(&sW[k][tx * 8 + 4]);
            u64 bb[4];
            bb[0] = ((const u64*)&b0)[0];
            bb[1] = ((const u64*)&b0)[1];
            bb[2] = ((const u64*)&b1)[0];
            bb[3] = ((const u64*)&b1)[1];
#pragma unroll
            for (int i = 0; i < 8; i++) {
                u64 aa = dup2(a[i]);
#pragma unroll
                for (int j = 0; j < 4; j++)
                    acc2[i][j] = ffma2(aa, bb[j], acc2[i][j]);
            }
        }
    }

#pragma unroll
    for (int i = 0; i < 8; i++) {
        int r = rb + ty * 8 + i;
        if (r < M) {
            *(float4*)(C + (size_t)r * HID + tx * 8)     = *(float4*)(&acc2[i][0]);
            *(float4*)(C + (size_t)r * HID + tx * 8 + 4) = *(float4*)(&acc2[i][2]);
        }
    }
}

// ---- edge gather: m[e] = binv[e] * sum_{n in edge e} xw[n]   (warp per edge) ----
__global__ __launch_bounds__(256) void k_gather_e(const float* __restrict__ src,
                                                  float* __restrict__ dst) {
    int g = blockIdx.x * blockDim.x + threadIdx.x;
    int e = g >> 5;
    int lane = g & 31;
    if (e >= NN) return;
    int beg = g_offs[NN + e];
    int end = g_offs[NN + e + 1];
    float4 acc = make_float4(0.f, 0.f, 0.f, 0.f);
    int j = beg;
    for (; j + 1 < end; j += 2) {
        int n0 = g_csr[j];
        int n1 = g_csr[j + 1];
        float4 v0 = ((const float4*)src)[(size_t)n0 * 32 + lane];
        float4 v1 = ((const float4*)src)[(size_t)n1 * 32 + lane];
        acc.x += v0.x + v1.x;
        acc.y += v0.y + v1.y;
        acc.z += v0.z + v1.z;
        acc.w += v0.w + v1.w;
    }
    if (j < end) {
        int n0 = g_csr[j];
        float4 v0 = ((const float4*)src)[(size_t)n0 * 32 + lane];
        acc.x += v0.x; acc.y += v0.y; acc.z += v0.z; acc.w += v0.w;
    }
    float s = g_binv[e];
    acc.x *= s; acc.y *= s; acc.z *= s; acc.w *= s;
    ((float4*)dst)[(size_t)e * 32 + lane] = acc;
}

// ---- node gather: out[n] = prelu(dinv[n] * sum_{e ∋ n} m[e] + bias [+ xres]) ----
template <bool RES>
__global__ __launch_bounds__(256) void k_gather_n(const float* __restrict__ src,
                                                  const float* __restrict__ bias,
                                                  const float* __restrict__ pa,
                                                  const float* __restrict__ xres,
                                                  float* __restrict__ dst) {
    int g = blockIdx.x * blockDim.x + threadIdx.x;
    int n = g >> 5;
    int lane = g & 31;
    if (n >= NN) return;
    int beg = g_offs[n];
    int end = g_offs[n + 1];
    float4 acc = make_float4(0.f, 0.f, 0.f, 0.f);
    int j = beg;
    for (; j + 1 < end; j += 2) {
        int e0 = g_csr[j];
        int e1 = g_csr[j + 1];
        float4 v0 = ((const float4*)src)[(size_t)e0 * 32 + lane];
        float4 v1 = ((const float4*)src)[(size_t)e1 * 32 + lane];
        acc.x += v0.x + v1.x;
        acc.y += v0.y + v1.y;
        acc.z += v0.z + v1.z;
        acc.w += v0.w + v1.w;
    }
    if (j < end) {
        int e0 = g_csr[j];
        float4 v0 = ((const float4*)src)[(size_t)e0 * 32 + lane];
        acc.x += v0.x; acc.y += v0.y; acc.z += v0.z; acc.w += v0.w;
    }
    float d = g_dinv[n];
    float a = pa[0];
    float4 b = ((const float4*)bias)[lane];
    acc.x = acc.x * d + b.x;
    acc.y = acc.y * d + b.y;
    acc.z = acc.z * d + b.z;
    acc.w = acc.w * d + b.w;
    if (RES) {
        float4 xv = ((const float4*)xres)[(size_t)n * 32 + lane];
        acc.x += xv.x; acc.y += xv.y; acc.z += xv.z; acc.w += xv.w;
    }
    acc.x = acc.x >= 0.f ? acc.x : a * acc.x;
    acc.y = acc.y >= 0.f ? acc.y : a * acc.y;
    acc.z = acc.z >= 0.f ? acc.z : a * acc.z;
    acc.w = acc.w >= 0.f ? acc.w : a * acc.w;
    ((float4*)dst)[(size_t)n * 32 + lane] = acc;
}

extern "C" void kernel_launch(void* const* d_in, const int* in_sizes, int n_in,
                              void* d_out, int out_size) {
    (void)in_sizes; (void)n_in; (void)out_size;
    const float* x   = (const float*)d_in[0];
    const void*  hei = d_in[1];
    const float* W1  = (const float*)d_in[2];
    const float* b1  = (const float*)d_in[3];
    const float* W2  = (const float*)d_in[4];
    const float* b2  = (const float*)d_in[5];
    const float* pa  = (const float*)d_in[6];
    float* out = (float*)d_out;

    float *pxw, *pm, *ph;
    cudaGetSymbolAddress((void**)&pxw, g_xw);
    cudaGetSymbolAddress((void**)&pm,  g_m);
    cudaGetSymbolAddress((void**)&ph,  g_h);

    const int GW_BLOCKS = (NN * 32) / 256;  // 6250: warp-per-segment grids

    // fork point: GEMM1 (on side stream) runs concurrently with prep (stream 0)
    cudaEventRecord(g_ss.evStart, 0);
    cudaStreamWaitEvent(g_ss.s, g_ss.evStart, 0);

    // prep on stream 0
    k_zero<<<(2 * NN + 255) / 256, 256>>>();
    k_detect<<<16, 256>>>((const long long*)hei);
    k_idx_deg<<<(NE / 2 + 255) / 256, 256>>>(hei);
    k_scan_one<<<1, SONE_T>>>();
    k_fill<<<(NE + 255) / 256, 256>>>();

    // GEMM1 on side stream (independent of prep)
    k_gemm<<<(NN + 127) / 128, 256, 0, g_ss.s>>>(x, W1, pxw, NN);
    cudaEventRecord(g_ss.evGemm, g_ss.s);
    cudaStreamWaitEvent(0, g_ss.evGemm, 0);  // join before gathers

    // ---- layer 1 aggregation ----
    k_gather_e<<<GW_BLOCKS, 256>>>(pxw, pm);
    k_gather_n<false><<<GW_BLOCKS, 256>>>(pm, b1, pa, nullptr, ph);

    // ---- layer 2 ----
    k_gemm<<<(NN + 127) / 128, 256>>>(ph, W2, pxw, NN);
    k_gather_e<<<GW_BLOCKS, 256>>>(pxw, pm);
    k_gather_n<true><<<GW_BLOCKS, 256>>>(pm, b2, pa, x, out);
}

// round 6
// speedup vs baseline: 1.7438x; 1.7438x over previous
#include <cuda_runtime.h>

#define NN 50000
#define NE 600000
#define HID 128

#define SCAN_BS 256
#define SCAN_VT 8
#define SCAN_ELEMS (SCAN_BS * SCAN_VT)              // 2048
#define SCAN_NBLK ((2 * NN + SCAN_ELEMS - 1) / SCAN_ELEMS)  // 49

typedef unsigned long long u64;

// ---- scratch (static device allocations; no cudaMalloc allowed) ----
__device__ int   g_ni[NE];
__device__ int   g_ei[NE];
__device__ int   g_cnt[2 * NN];       // [0,NN): node degree D; [NN,2NN): hedge degree B
__device__ int   g_offs[2 * NN + 1];  // combined exclusive offsets
__device__ int   g_bsum[64];
__device__ int   g_csr[2 * NE];       // node rows hold edge ids; edge rows hold node ids
__device__ float g_dinv[NN];
__device__ float g_binv[NN];
__device__ float g_xw[NN * HID];
__device__ float g_m[NN * HID];
__device__ float g_h[NN * HID];
__device__ int   g_is_i32;

// ---- side stream + events for forked capture ----
struct SideStream {
    cudaStream_t s;
    cudaEvent_t evStart, evGemm;
    SideStream() {
        cudaStreamCreateWithFlags(&s, cudaStreamNonBlocking);
        cudaEventCreateWithFlags(&evStart, cudaEventDisableTiming);
        cudaEventCreateWithFlags(&evGemm, cudaEventDisableTiming);
    }
};
static SideStream g_ss;

// ---- packed f32x2 helpers ----
__device__ __forceinline__ u64 ffma2(u64 a, u64 b, u64 c) {
    u64 d;
    asm("fma.rn.f32x2 %0, %1, %2, %3;" : "=l"(d) : "l"(a), "l"(b), "l"(c));
    return d;
}
__device__ __forceinline__ u64 dup2(float x) {
    u64 d;
    asm("mov.b64 %0, {%1, %1};" : "=l"(d) : "f"(x));
    return d;
}

// ---- zero counts + flag ----
__global__ void k_zero() {
    int i = blockIdx.x * blockDim.x + threadIdx.x;
    if (i < 2 * NN) g_cnt[i] = 0;
    if (i == 0) g_is_i32 = 0;
}

__global__ void k_detect(const long long* __restrict__ hei64) {
    int i = blockIdx.x * blockDim.x + threadIdx.x;
    if (i < 4096) {
        long long v = hei64[i];
        if (v < 0 || v >= NN) atomicExch(&g_is_i32, 1);
    }
}

// ---- index decode + degree counts (2 entries / thread) ----
__global__ void k_idx_deg(const void* __restrict__ hei) {
    int t = blockIdx.x * blockDim.x + threadIdx.x;
    int i0 = t * 2;
    if (i0 >= NE) return;
    bool i32 = (g_is_i32 != 0);
#pragma unroll
    for (int k = 0; k < 2; k++) {
        int i = i0 + k;
        if (i >= NE) break;
        int n, e;
        if (i32) {
            const int* h32 = (const int*)hei;
            n = h32[i];
            e = h32[NE + i];
        } else {
            const long long* h64 = (const long long*)hei;
            n = (int)h64[i];
            e = (int)h64[NE + i];
        }
        if (n < 0 || n >= NN) n = 0;
        if (e < 0 || e >= NN) e = 0;
        g_ni[i] = n;
        g_ei[i] = e;
        atomicAdd(&g_cnt[n], 1);
        atomicAdd(&g_cnt[NN + e], 1);
    }
}

// ---- exclusive scan over g_cnt[0 : 2NN] -> g_offs (3-kernel, multi-block) ----
__global__ __launch_bounds__(SCAN_BS) void k_scanA() {
    __shared__ int s[SCAN_BS];
    int blk = blockIdx.x, tid = threadIdx.x;
    int base = blk * SCAN_ELEMS + tid * SCAN_VT;
    int v[SCAN_VT];
    int sum = 0;
#pragma unroll
    for (int t = 0; t < SCAN_VT; t++) {
        v[t] = (base + t < 2 * NN) ? g_cnt[base + t] : 0;
        sum += v[t];
    }
    s[tid] = sum;
    __syncthreads();
    for (int off = 1; off < SCAN_BS; off <<= 1) {
        int t = (tid >= off) ? s[tid - off] : 0;
        __syncthreads();
        s[tid] += t;
        __syncthreads();
    }
    if (tid == SCAN_BS - 1) g_bsum[blk] = s[tid];
    int run = s[tid] - sum;
#pragma unroll
    for (int t = 0; t < SCAN_VT; t++) {
        if (base + t < 2 * NN) g_offs[base + t] = run;
        run += v[t];
    }
}

__global__ void k_scanB() {
    __shared__ int sh[64];
    int tid = threadIdx.x;
    int v = (tid < SCAN_NBLK) ? g_bsum[tid] : 0;
    sh[tid] = v;
    __syncthreads();
    for (int off = 1; off < 64; off <<= 1) {
        int t = (tid >= off) ? sh[tid - off] : 0;
        __syncthreads();
        sh[tid] += t;
        __syncthreads();
    }
    if (tid < SCAN_NBLK) g_bsum[tid] = sh[tid] - v;  // exclusive
}

// ---- offsets finalize + inverse degrees (fused) ----
__global__ void k_scanC() {
    int i = blockIdx.x * blockDim.x + threadIdx.x;
    if (i < 2 * NN) {
        g_offs[i] += g_bsum[i / SCAN_ELEMS];
        int c = g_cnt[i];
        float inv = c > 0 ? 1.0f / (float)c : 0.0f;
        if (i < NN) g_dinv[i] = inv;
        else        g_binv[i - NN] = inv;
    }
    if (i == 0) g_offs[2 * NN] = 2 * NE;
}

// ---- CSR fill: consumes g_cnt as cursors via atomicSub ----
__global__ void k_fill() {
    int i = blockIdx.x * blockDim.x + threadIdx.x;
    if (i >= NE) return;
    int n = g_ni[i];
    int e = g_ei[i];
    int pn = g_offs[n] + atomicSub(&g_cnt[n], 1) - 1;
    g_csr[pn] = e;
    int pe = g_offs[NN + e] + atomicSub(&g_cnt[NN + e], 1) - 1;
    g_csr[pe] = n;
}

// ---- GEMM: C[M,128] = A[M,128] @ W[128,128], packed f32x2 FMA microkernel ----
__global__ __launch_bounds__(256) void k_gemm(const float* __restrict__ A,
                                              const float* __restrict__ W,
                                              float* __restrict__ C, int M) {
    __shared__ float sAT[32][129];
    __shared__ float sW[32][128];
    int tid = threadIdx.x;
    int tx = tid & 15;
    int ty = tid >> 4;
    int rb = blockIdx.x * 128;
    int lr = tid >> 3;
    int kq = tid & 7;

    u64 acc2[8][4];
#pragma unroll
    for (int i = 0; i < 8; i++)
#pragma unroll
        for (int j = 0; j < 4; j++) acc2[i][j] = 0ull;

    for (int kk = 0; kk < 128; kk += 32) {
        __syncthreads();
#pragma unroll
        for (int t = 0; t < 4; t++) {
            int r = lr + t * 32;
            float4 v = make_float4(0.f, 0.f, 0.f, 0.f);
            if (rb + r < M)
                v = *(const float4*)(A + (size_t)(rb + r) * HID + kk + kq * 4);
            sAT[kq * 4 + 0][r] = v.x;
            sAT[kq * 4 + 1][r] = v.y;
            sAT[kq * 4 + 2][r] = v.z;
            sAT[kq * 4 + 3][r] = v.w;
        }
#pragma unroll
        for (int t = 0; t < 4; t++) {
            int i4 = tid + t * 256;
            int k = i4 >> 5, c4 = i4 & 31;
            *(float4*)(&sW[k][c4 * 4]) =
                *(const float4*)(W + (size_t)(kk + k) * HID + c4 * 4);
        }
        __syncthreads();

#pragma unroll
        for (int k = 0; k < 32; k++) {
            float a[8];
#pragma unroll
            for (int i = 0; i < 8; i++) a[i] = sAT[k][ty * 8 + i];
            float4 b0 = *(const float4*)(&sW[k][tx * 8]);
            float4 b1 = *(const float4*)(&sW[k][tx * 8 + 4]);
            u64 bb[4];
            bb[0] = ((const u64*)&b0)[0];
            bb[1] = ((const u64*)&b0)[1];
            bb[2] = ((const u64*)&b1)[0];
            bb[3] = ((const u64*)&b1)[1];
#pragma unroll
            for (int i = 0; i < 8; i++) {
                u64 aa = dup2(a[i]);
#pragma unroll
                for (int j = 0; j < 4; j++)
                    acc2[i][j] = ffma2(aa, bb[j], acc2[i][j]);
            }
        }
    }

#pragma unroll
    for (int i = 0; i < 8; i++) {
        int r = rb + ty * 8 + i;
        if (r < M) {
            *(float4*)(C + (size_t)r * HID + tx * 8)     = *(float4*)(&acc2[i][0]);
            *(float4*)(C + (size_t)r * HID + tx * 8 + 4) = *(float4*)(&acc2[i][2]);
        }
    }
}

// ---- edge gather: m[e] = binv[e] * sum_{n in edge e} xw[n]   (warp per edge) ----
__global__ __launch_bounds__(256) void k_gather_e(const float* __restrict__ src,
                                                  float* __restrict__ dst) {
    int g = blockIdx.x * blockDim.x + threadIdx.x;
    int e = g >> 5;
    int lane = g & 31;
    if (e >= NN) return;
    int beg = g_offs[NN + e];
    int end = g_offs[NN + e + 1];
    float4 acc = make_float4(0.f, 0.f, 0.f, 0.f);
    int j = beg;
    for (; j + 1 < end; j += 2) {
        int n0 = g_csr[j];
        int n1 = g_csr[j + 1];
        float4 v0 = ((const float4*)src)[(size_t)n0 * 32 + lane];
        float4 v1 = ((const float4*)src)[(size_t)n1 * 32 + lane];
        acc.x += v0.x + v1.x;
        acc.y += v0.y + v1.y;
        acc.z += v0.z + v1.z;
        acc.w += v0.w + v1.w;
    }
    if (j < end) {
        int n0 = g_csr[j];
        float4 v0 = ((const float4*)src)[(size_t)n0 * 32 + lane];
        acc.x += v0.x; acc.y += v0.y; acc.z += v0.z; acc.w += v0.w;
    }
    float s = g_binv[e];
    acc.x *= s; acc.y *= s; acc.z *= s; acc.w *= s;
    ((float4*)dst)[(size_t)e * 32 + lane] = acc;
}

// ---- node gather: out[n] = prelu(dinv[n] * sum_{e ∋ n} m[e] + bias [+ xres]) ----
template <bool RES>
__global__ __launch_bounds__(256) void k_gather_n(const float* __restrict__ src,
                                                  const float* __restrict__ bias,
                                                  const float* __restrict__ pa,
                                                  const float* __restrict__ xres,
                                                  float* __restrict__ dst) {
    int g = blockIdx.x * blockDim.x + threadIdx.x;
    int n = g >> 5;
    int lane = g & 31;
    if (n >= NN) return;
    int beg = g_offs[n];
    int end = g_offs[n + 1];
    float4 acc = make_float4(0.f, 0.f, 0.f, 0.f);
    int j = beg;
    for (; j + 1 < end; j += 2) {
        int e0 = g_csr[j];
        int e1 = g_csr[j + 1];
        float4 v0 = ((const float4*)src)[(size_t)e0 * 32 + lane];
        float4 v1 = ((const float4*)src)[(size_t)e1 * 32 + lane];
        acc.x += v0.x + v1.x;
        acc.y += v0.y + v1.y;
        acc.z += v0.z + v1.z;
        acc.w += v0.w + v1.w;
    }
    if (j < end) {
        int e0 = g_csr[j];
        float4 v0 = ((const float4*)src)[(size_t)e0 * 32 + lane];
        acc.x += v0.x; acc.y += v0.y; acc.z += v0.z; acc.w += v0.w;
    }
    float d = g_dinv[n];
    float a = pa[0];
    float4 b = ((const float4*)bias)[lane];
    acc.x = acc.x * d + b.x;
    acc.y = acc.y * d + b.y;
    acc.z = acc.z * d + b.z;
    acc.w = acc.w * d + b.w;
    if (RES) {
        float4 xv = ((const float4*)xres)[(size_t)n * 32 + lane];
        acc.x += xv.x; acc.y += xv.y; acc.z += xv.z; acc.w += xv.w;
    }
    acc.x = acc.x >= 0.f ? acc.x : a * acc.x;
    acc.y = acc.y >= 0.f ? acc.y : a * acc.y;
    acc.z = acc.z >= 0.f ? acc.z : a * acc.z;
    acc.w = acc.w >= 0.f ? acc.w : a * acc.w;
    ((float4*)dst)[(size_t)n * 32 + lane] = acc;
}

extern "C" void kernel_launch(void* const* d_in, const int* in_sizes, int n_in,
                              void* d_out, int out_size) {
    (void)in_sizes; (void)n_in; (void)out_size;
    const float* x   = (const float*)d_in[0];
    const void*  hei = d_in[1];
    const float* W1  = (const float*)d_in[2];
    const float* b1  = (const float*)d_in[3];
    const float* W2  = (const float*)d_in[4];
    const float* b2  = (const float*)d_in[5];
    const float* pa  = (const float*)d_in[6];
    float* out = (float*)d_out;

    float *pxw, *pm, *ph;
    cudaGetSymbolAddress((void**)&pxw, g_xw);
    cudaGetSymbolAddress((void**)&pm,  g_m);
    cudaGetSymbolAddress((void**)&ph,  g_h);

    const int GW_BLOCKS = (NN * 32) / 256;  // 6250: warp-per-segment grids

    // fork point: GEMM1 (on side stream) runs concurrently with prep (stream 0)
    cudaEventRecord(g_ss.evStart, 0);
    cudaStreamWaitEvent(g_ss.s, g_ss.evStart, 0);

    // prep on stream 0
    k_zero<<<(2 * NN + 255) / 256, 256>>>();
    k_detect<<<16, 256>>>((const long long*)hei);
    k_idx_deg<<<(NE / 2 + 255) / 256, 256>>>(hei);
    k_scanA<<<SCAN_NBLK, SCAN_BS>>>();
    k_scanB<<<1, 64>>>();
    k_scanC<<<(2 * NN + 255) / 256, 256>>>();
    k_fill<<<(NE + 255) / 256, 256>>>();

    // GEMM1 on side stream (independent of prep)
    k_gemm<<<(NN + 127) / 128, 256, 0, g_ss.s>>>(x, W1, pxw, NN);
    cudaEventRecord(g_ss.evGemm, g_ss.s);
    cudaStreamWaitEvent(0, g_ss.evGemm, 0);  // join before gathers

    // ---- layer 1 aggregation ----
    k_gather_e<<<GW_BLOCKS, 256>>>(pxw, pm);
    k_gather_n<false><<<GW_BLOCKS, 256>>>(pm, b1, pa, nullptr, ph);

    // ---- layer 2 ----
    k_gemm<<<(NN + 127) / 128, 256>>>(ph, W2, pxw, NN);
    k_gather_e<<<GW_BLOCKS, 256>>>(pxw, pm);
    k_gather_n<true><<<GW_BLOCKS, 256>>>(pm, b2, pa, x, out);
}

// round 7
// speedup vs baseline: 1.9248x; 1.1038x over previous
#include <cuda_runtime.h>
#include <cuda_fp16.h>

#define NN 50000
#define NE 600000
#define HID 128

#define SCAN_BS 256
#define SCAN_VT 8
#define SCAN_ELEMS (SCAN_BS * SCAN_VT)              // 2048
#define SCAN_NBLK ((2 * NN + SCAN_ELEMS - 1) / SCAN_ELEMS)  // 49

typedef unsigned long long u64;

// ---- scratch (static device allocations; no cudaMalloc allowed) ----
__device__ int    g_ni[NE];
__device__ int    g_ei[NE];
__device__ int    g_cnt[2 * NN];
__device__ int    g_offs[2 * NN + 1];
__device__ int    g_bsum[64];
__device__ int    g_csr[2 * NE];
__device__ float  g_dinv[NN];
__device__ float  g_binv[NN];
__device__ __half g_xw[NN * HID];   // GEMM output, fp16 (gathered operand)
__device__ __half g_m[NN * HID];    // edge aggregate, fp16 (gathered operand)
__device__ float  g_h[NN * HID];    // layer-1 output, fp32 (GEMM2 input)
__device__ int    g_is_i32;

// ---- side stream + events for forked capture ----
struct SideStream {
    cudaStream_t s;
    cudaEvent_t evStart, evGemm;
    SideStream() {
        cudaStreamCreateWithFlags(&s, cudaStreamNonBlocking);
        cudaEventCreateWithFlags(&evStart, cudaEventDisableTiming);
        cudaEventCreateWithFlags(&evGemm, cudaEventDisableTiming);
    }
};
static SideStream g_ss;

// ---- packed f32x2 helpers ----
__device__ __forceinline__ u64 ffma2(u64 a, u64 b, u64 c) {
    u64 d;
    asm("fma.rn.f32x2 %0, %1, %2, %3;" : "=l"(d) : "l"(a), "l"(b), "l"(c));
    return d;
}
__device__ __forceinline__ u64 dup2(float x) {
    u64 d;
    asm("mov.b64 %0, {%1, %1};" : "=l"(d) : "f"(x));
    return d;
}
__device__ __forceinline__ float2 u64_f2(u64 v) {
    float2 f;
    asm("mov.b64 {%0, %1}, %2;" : "=f"(f.x), "=f"(f.y) : "l"(v));
    return f;
}

// ---- zero counts + flag ----
__global__ void k_zero() {
    int i = blockIdx.x * blockDim.x + threadIdx.x;
    if (i < 2 * NN) g_cnt[i] = 0;
    if (i == 0) g_is_i32 = 0;
}

__global__ void k_detect(const long long* __restrict__ hei64) {
    int i = blockIdx.x * blockDim.x + threadIdx.x;
    if (i < 4096) {
        long long v = hei64[i];
        if (v < 0 || v >= NN) atomicExch(&g_is_i32, 1);
    }
}

// ---- index decode + degree counts (2 entries / thread) ----
__global__ void k_idx_deg(const void* __restrict__ hei) {
    int t = blockIdx.x * blockDim.x + threadIdx.x;
    int i0 = t * 2;
    if (i0 >= NE) return;
    bool i32 = (g_is_i32 != 0);
#pragma unroll
    for (int k = 0; k < 2; k++) {
        int i = i0 + k;
        if (i >= NE) break;
        int n, e;
        if (i32) {
            const int* h32 = (const int*)hei;
            n = h32[i];
            e = h32[NE + i];
        } else {
            const long long* h64 = (const long long*)hei;
            n = (int)h64[i];
            e = (int)h64[NE + i];
        }
        if (n < 0 || n >= NN) n = 0;
        if (e < 0 || e >= NN) e = 0;
        g_ni[i] = n;
        g_ei[i] = e;
        atomicAdd(&g_cnt[n], 1);
        atomicAdd(&g_cnt[NN + e], 1);
    }
}

// ---- exclusive scan over g_cnt[0 : 2NN] -> g_offs (3-kernel, multi-block) ----
__global__ __launch_bounds__(SCAN_BS) void k_scanA() {
    __shared__ int s[SCAN_BS];
    int blk = blockIdx.x, tid = threadIdx.x;
    int base = blk * SCAN_ELEMS + tid * SCAN_VT;
    int v[SCAN_VT];
    int sum = 0;
#pragma unroll
    for (int t = 0; t < SCAN_VT; t++) {
        v[t] = (base + t < 2 * NN) ? g_cnt[base + t] : 0;
        sum += v[t];
    }
    s[tid] = sum;
    __syncthreads();
    for (int off = 1; off < SCAN_BS; off <<= 1) {
        int t = (tid >= off) ? s[tid - off] : 0;
        __syncthreads();
        s[tid] += t;
        __syncthreads();
    }
    if (tid == SCAN_BS - 1) g_bsum[blk] = s[tid];
    int run = s[tid] - sum;
#pragma unroll
    for (int t = 0; t < SCAN_VT; t++) {
        if (base + t < 2 * NN) g_offs[base + t] = run;
        run += v[t];
    }
}

__global__ void k_scanB() {
    __shared__ int sh[64];
    int tid = threadIdx.x;
    int v = (tid < SCAN_NBLK) ? g_bsum[tid] : 0;
    sh[tid] = v;
    __syncthreads();
    for (int off = 1; off < 64; off <<= 1) {
        int t = (tid >= off) ? sh[tid - off] : 0;
        __syncthreads();
        sh[tid] += t;
        __syncthreads();
    }
    if (tid < SCAN_NBLK) g_bsum[tid] = sh[tid] - v;
}

__global__ void k_scanC() {
    int i = blockIdx.x * blockDim.x + threadIdx.x;
    if (i < 2 * NN) {
        g_offs[i] += g_bsum[i / SCAN_ELEMS];
        int c = g_cnt[i];
        float inv = c > 0 ? 1.0f / (float)c : 0.0f;
        if (i < NN) g_dinv[i] = inv;
        else        g_binv[i - NN] = inv;
    }
    if (i == 0) g_offs[2 * NN] = 2 * NE;
}

// ---- CSR fill ----
__global__ void k_fill() {
    int i = blockIdx.x * blockDim.x + threadIdx.x;
    if (i >= NE) return;
    int n = g_ni[i];
    int e = g_ei[i];
    int pn = g_offs[n] + atomicSub(&g_cnt[n], 1) - 1;
    g_csr[pn] = e;
    int pe = g_offs[NN + e] + atomicSub(&g_cnt[NN + e], 1) - 1;
    g_csr[pe] = n;
}

// ---- GEMM: C[M,128](fp16) = A[M,128](fp32) @ W[128,128](fp32) ----
__global__ __launch_bounds__(256) void k_gemm(const float* __restrict__ A,
                                              const float* __restrict__ W,
                                              __half* __restrict__ C, int M) {
    __shared__ float sAT[32][129];
    __shared__ float sW[32][128];
    int tid = threadIdx.x;
    int tx = tid & 15;
    int ty = tid >> 4;
    int rb = blockIdx.x * 128;
    int lr = tid >> 3;
    int kq = tid & 7;

    u64 acc2[8][4];
#pragma unroll
    for (int i = 0; i < 8; i++)
#pragma unroll
        for (int j = 0; j < 4; j++) acc2[i][j] = 0ull;

    for (int kk = 0; kk < 128; kk += 32) {
        __syncthreads();
#pragma unroll
        for (int t = 0; t < 4; t++) {
            int r = lr + t * 32;
            float4 v = make_float4(0.f, 0.f, 0.f, 0.f);
            if (rb + r < M)
                v = *(const float4*)(A + (size_t)(rb + r) * HID + kk + kq * 4);
            sAT[kq * 4 + 0][r] = v.x;
            sAT[kq * 4 + 1][r] = v.y;
            sAT[kq * 4 + 2][r] = v.z;
            sAT[kq * 4 + 3][r] = v.w;
        }
#pragma unroll
        for (int t = 0; t < 4; t++) {
            int i4 = tid + t * 256;
            int k = i4 >> 5, c4 = i4 & 31;
            *(float4*)(&sW[k][c4 * 4]) =
                *(const float4*)(W + (size_t)(kk + k) * HID + c4 * 4);
        }
        __syncthreads();

#pragma unroll
        for (int k = 0; k < 32; k++) {
            float a[8];
#pragma unroll
            for (int i = 0; i < 8; i++) a[i] = sAT[k][ty * 8 + i];
            float4 b0 = *(const float4*)(&sW[k][tx * 8]);
            float4 b1 = *(const float4*)(&sW[k][tx * 8 + 4]);
            u64 bb[4];
            bb[0] = ((const u64*)&b0)[0];
            bb[1] = ((const u64*)&b0)[1];
            bb[2] = ((const u64*)&b1)[0];
            bb[3] = ((const u64*)&b1)[1];
#pragma unroll
            for (int i = 0; i < 8; i++) {
                u64 aa = dup2(a[i]);
#pragma unroll
                for (int j = 0; j < 4; j++)
                    acc2[i][j] = ffma2(aa, bb[j], acc2[i][j]);
            }
        }
    }

#pragma unroll
    for (int i = 0; i < 8; i++) {
        int r = rb + ty * 8 + i;
        if (r < M) {
            __half2 hv[4];
#pragma unroll
            for (int j = 0; j < 4; j++) {
                float2 f = u64_f2(acc2[i][j]);
                hv[j] = __floats2half2_rn(f.x, f.y);
            }
            *(uint4*)(C + (size_t)r * HID + tx * 8) = *(uint4*)hv;
        }
    }
}

// ---- edge gather (fp16 in / fp16 out): m[e] = binv[e] * sum xw[n] ----
__global__ __launch_bounds__(256) void k_gather_e(const __half* __restrict__ src,
                                                  __half* __restrict__ dst) {
    int g = blockIdx.x * blockDim.x + threadIdx.x;
    int e = g >> 5;
    int lane = g & 31;
    if (e >= NN) return;
    int beg = g_offs[NN + e];
    int end = g_offs[NN + e + 1];
    float4 acc = make_float4(0.f, 0.f, 0.f, 0.f);
    const uint2* s2 = (const uint2*)src;  // row = 32 uint2 (4 halfs each)
    int j = beg;
    for (; j + 1 < end; j += 2) {
        int n0 = g_csr[j];
        int n1 = g_csr[j + 1];
        uint2 u0 = s2[(size_t)n0 * 32 + lane];
        uint2 u1 = s2[(size_t)n1 * 32 + lane];
        float2 a0 = __half22float2(*(const __half2*)&u0.x);
        float2 a1 = __half22float2(*(const __half2*)&u0.y);
        float2 b0 = __half22float2(*(const __half2*)&u1.x);
        float2 b1 = __half22float2(*(const __half2*)&u1.y);
        acc.x += a0.x + b0.x;
        acc.y += a0.y + b0.y;
        acc.z += a1.x + b1.x;
        acc.w += a1.y + b1.y;
    }
    if (j < end) {
        int n0 = g_csr[j];
        uint2 u0 = s2[(size_t)n0 * 32 + lane];
        float2 a0 = __half22float2(*(const __half2*)&u0.x);
        float2 a1 = __half22float2(*(const __half2*)&u0.y);
        acc.x += a0.x; acc.y += a0.y; acc.z += a1.x; acc.w += a1.y;
    }
    float s = g_binv[e];
    __half2 o0 = __floats2half2_rn(acc.x * s, acc.y * s);
    __half2 o1 = __floats2half2_rn(acc.z * s, acc.w * s);
    uint2 ov;
    ov.x = *(const unsigned*)&o0;
    ov.y = *(const unsigned*)&o1;
    ((uint2*)dst)[(size_t)e * 32 + lane] = ov;
}

// ---- node gather (fp16 in / fp32 out): out[n] = prelu(dinv*sum m[e] + bias [+x]) ----
template <bool RES>
__global__ __launch_bounds__(256) void k_gather_n(const __half* __restrict__ src,
                                                  const float* __restrict__ bias,
                                                  const float* __restrict__ pa,
                                                  const float* __restrict__ xres,
                                                  float* __restrict__ dst) {
    int g = blockIdx.x * blockDim.x + threadIdx.x;
    int n = g >> 5;
    int lane = g & 31;
    if (n >= NN) return;
    int beg = g_offs[n];
    int end = g_offs[n + 1];
    float4 acc = make_float4(0.f, 0.f, 0.f, 0.f);
    const uint2* s2 = (const uint2*)src;
    int j = beg;
    for (; j + 1 < end; j += 2) {
        int e0 = g_csr[j];
        int e1 = g_csr[j + 1];
        uint2 u0 = s2[(size_t)e0 * 32 + lane];
        uint2 u1 = s2[(size_t)e1 * 32 + lane];
        float2 a0 = __half22float2(*(const __half2*)&u0.x);
        float2 a1 = __half22float2(*(const __half2*)&u0.y);
        float2 b0 = __half22float2(*(const __half2*)&u1.x);
        float2 b1 = __half22float2(*(const __half2*)&u1.y);
        acc.x += a0.x + b0.x;
        acc.y += a0.y + b0.y;
        acc.z += a1.x + b1.x;
        acc.w += a1.y + b1.y;
    }
    if (j < end) {
        int e0 = g_csr[j];
        uint2 u0 = s2[(size_t)e0 * 32 + lane];
        float2 a0 = __half22float2(*(const __half2*)&u0.x);
        float2 a1 = __half22float2(*(const __half2*)&u0.y);
        acc.x += a0.x; acc.y += a0.y; acc.z += a1.x; acc.w += a1.y;
    }
    float d = g_dinv[n];
    float a = pa[0];
    // bias layout: 4 consecutive floats per lane (cols lane*4 .. lane*4+3)
    float4 b = ((const float4*)bias)[lane];
    acc.x = acc.x * d + b.x;
    acc.y = acc.y * d + b.y;
    acc.z = acc.z * d + b.z;
    acc.w = acc.w * d + b.w;
    if (RES) {
        float4 xv = ((const float4*)xres)[(size_t)n * 32 + lane];
        acc.x += xv.x; acc.y += xv.y; acc.z += xv.z; acc.w += xv.w;
    }
    acc.x = acc.x >= 0.f ? acc.x : a * acc.x;
    acc.y = acc.y >= 0.f ? acc.y : a * acc.y;
    acc.z = acc.z >= 0.f ? acc.z : a * acc.z;
    acc.w = acc.w >= 0.f ? acc.w : a * acc.w;
    ((float4*)dst)[(size_t)n * 32 + lane] = acc;
}

extern "C" void kernel_launch(void* const* d_in, const int* in_sizes, int n_in,
                              void* d_out, int out_size) {
    (void)in_sizes; (void)n_in; (void)out_size;
    const float* x   = (const float*)d_in[0];
    const void*  hei = d_in[1];
    const float* W1  = (const float*)d_in[2];
    const float* b1  = (const float*)d_in[3];
    const float* W2  = (const float*)d_in[4];
    const float* b2  = (const float*)d_in[5];
    const float* pa  = (const float*)d_in[6];
    float* out = (float*)d_out;

    __half *pxw, *pm;
    float *ph;
    cudaGetSymbolAddress((void**)&pxw, g_xw);
    cudaGetSymbolAddress((void**)&pm,  g_m);
    cudaGetSymbolAddress((void**)&ph,  g_h);

    const int GW_BLOCKS = (NN * 32) / 256;

    // fork: GEMM1 (side stream) || prep (stream 0)
    cudaEventRecord(g_ss.evStart, 0);
    cudaStreamWaitEvent(g_ss.s, g_ss.evStart, 0);

    k_zero<<<(2 * NN + 255) / 256, 256>>>();
    k_detect<<<16, 256>>>((const long long*)hei);
    k_idx_deg<<<(NE / 2 + 255) / 256, 256>>>(hei);
    k_scanA<<<SCAN_NBLK, SCAN_BS>>>();
    k_scanB<<<1, 64>>>();
    k_scanC<<<(2 * NN + 255) / 256, 256>>>();
    k_fill<<<(NE + 255) / 256, 256>>>();

    k_gemm<<<(NN + 127) / 128, 256, 0, g_ss.s>>>(x, W1, pxw, NN);
    cudaEventRecord(g_ss.evGemm, g_ss.s);
    cudaStreamWaitEvent(0, g_ss.evGemm, 0);

    // ---- layer 1 aggregation ----
    k_gather_e<<<GW_BLOCKS, 256>>>(pxw, pm);
    k_gather_n<false><<<GW_BLOCKS, 256>>>(pm, b1, pa, nullptr, ph);

    // ---- layer 2 ----
    k_gemm<<<(NN + 127) / 128, 256>>>(ph, W2, pxw, NN);
    k_gather_e<<<GW_BLOCKS, 256>>>(pxw, pm);
    k_gather_n<true><<<GW_BLOCKS, 256>>>(pm, b2, pa, x, out);
}

// round 8
// speedup vs baseline: 2.5970x; 1.3492x over previous
#include <cuda_runtime.h>
#include <cuda_fp16.h>

#define NN 50000
#define NE 600000
#define HID 128

#define SCAN_BS 256
#define SCAN_VT 8
#define SCAN_ELEMS (SCAN_BS * SCAN_VT)              // 2048
#define SCAN_NBLK ((2 * NN + SCAN_ELEMS - 1) / SCAN_ELEMS)  // 49

#define ASTRIDE 136  // smem row stride in halfs: 272B = 16 mod 128 -> conflict-free ldmatrix

typedef unsigned long long u64;
typedef unsigned int u32;

// ---- scratch (static device allocations; no cudaMalloc allowed) ----
__device__ int    g_cnt[2 * NN];
__device__ int    g_offs[2 * NN + 1];
__device__ int    g_bsum[64];
__device__ int    g_csr[2 * NE];
__device__ float  g_dinv[NN];
__device__ float  g_binv[NN];
__device__ __half g_xh[NN * HID];    // fp16 copy of x (GEMM1 input)
__device__ __half g_w1h[HID * HID];
__device__ __half g_w2h[HID * HID];
__device__ __half g_xw[NN * HID];    // GEMM output (gathered)
__device__ __half g_m[NN * HID];     // edge aggregate (gathered)
__device__ __half g_h[NN * HID];     // layer-1 output (GEMM2 input)
__device__ int    g_is_i32;

// ---- side stream + events for forked capture ----
struct SideStream {
    cudaStream_t s;
    cudaEvent_t evStart, evGemm;
    SideStream() {
        cudaStreamCreateWithFlags(&s, cudaStreamNonBlocking);
        cudaEventCreateWithFlags(&evStart, cudaEventDisableTiming);
        cudaEventCreateWithFlags(&evGemm, cudaEventDisableTiming);
    }
};
static SideStream g_ss;

// ---- PTX helpers ----
__device__ __forceinline__ u32 sptr(const void* p) {
    return (u32)__cvta_generic_to_shared(p);
}
__device__ __forceinline__ void ldsm4(u32& r0, u32& r1, u32& r2, u32& r3, u32 a) {
    asm volatile("ldmatrix.sync.aligned.m8n8.x4.shared.b16 {%0,%1,%2,%3},[%4];"
                 : "=r"(r0), "=r"(r1), "=r"(r2), "=r"(r3) : "r"(a));
}
__device__ __forceinline__ void ldsm4t(u32& r0, u32& r1, u32& r2, u32& r3, u32 a) {
    asm volatile("ldmatrix.sync.aligned.m8n8.x4.trans.shared.b16 {%0,%1,%2,%3},[%4];"
                 : "=r"(r0), "=r"(r1), "=r"(r2), "=r"(r3) : "r"(a));
}
__device__ __forceinline__ void mma16816(float* d, const u32* a, const u32* b) {
    asm volatile("mma.sync.aligned.m16n8k16.row.col.f32.f16.f16.f32 "
                 "{%0,%1,%2,%3},{%4,%5,%6,%7},{%8,%9},{%0,%1,%2,%3};"
                 : "+f"(d[0]), "+f"(d[1]), "+f"(d[2]), "+f"(d[3])
                 : "r"(a[0]), "r"(a[1]), "r"(a[2]), "r"(a[3]), "r"(b[0]), "r"(b[1]));
}

// ---- zero counts + flag ----
__global__ void k_zero() {
    int i = blockIdx.x * blockDim.x + threadIdx.x;
    if (i < 2 * NN) g_cnt[i] = 0;
    if (i == 0) g_is_i32 = 0;
}

__global__ void k_detect(const long long* __restrict__ hei64) {
    int i = blockIdx.x * blockDim.x + threadIdx.x;
    if (i < 4096) {
        long long v = hei64[i];
        if (v < 0 || v >= NN) atomicExch(&g_is_i32, 1);
    }
}

__device__ __forceinline__ void decode(const void* hei, bool i32, int i, int& n, int& e) {
    if (i32) {
        n = ((const int*)hei)[i];
        e = ((const int*)hei)[NE + i];
    } else {
        n = (int)((const long long*)hei)[i];
        e = (int)((const long long*)hei)[NE + i];
    }
    if (n < 0 || n >= NN) n = 0;
    if (e < 0 || e >= NN) e = 0;
}

// ---- degree counts (2 entries / thread, no staging arrays) ----
__global__ void k_deg(const void* __restrict__ hei) {
    int t = blockIdx.x * blockDim.x + threadIdx.x;
    int i0 = t * 2;
    if (i0 >= NE) return;
    bool i32 = (g_is_i32 != 0);
#pragma unroll
    for (int k = 0; k < 2; k++) {
        int i = i0 + k;
        if (i >= NE) break;
        int n, e;
        decode(hei, i32, i, n, e);
        atomicAdd(&g_cnt[n], 1);
        atomicAdd(&g_cnt[NN + e], 1);
    }
}

// ---- exclusive scan over g_cnt[0 : 2NN] -> g_offs ----
__global__ __launch_bounds__(SCAN_BS) void k_scanA() {
    __shared__ int s[SCAN_BS];
    int blk = blockIdx.x, tid = threadIdx.x;
    int base = blk * SCAN_ELEMS + tid * SCAN_VT;
    int v[SCAN_VT];
    int sum = 0;
#pragma unroll
    for (int t = 0; t < SCAN_VT; t++) {
        v[t] = (base + t < 2 * NN) ? g_cnt[base + t] : 0;
        sum += v[t];
    }
    s[tid] = sum;
    __syncthreads();
    for (int off = 1; off < SCAN_BS; off <<= 1) {
        int t = (tid >= off) ? s[tid - off] : 0;
        __syncthreads();
        s[tid] += t;
        __syncthreads();
    }
    if (tid == SCAN_BS - 1) g_bsum[blk] = s[tid];
    int run = s[tid] - sum;
#pragma unroll
    for (int t = 0; t < SCAN_VT; t++) {
        if (base + t < 2 * NN) g_offs[base + t] = run;
        run += v[t];
    }
}

__global__ void k_scanB() {
    __shared__ int sh[64];
    int tid = threadIdx.x;
    int v = (tid < SCAN_NBLK) ? g_bsum[tid] : 0;
    sh[tid] = v;
    __syncthreads();
    for (int off = 1; off < 64; off <<= 1) {
        int t = (tid >= off) ? sh[tid - off] : 0;
        __syncthreads();
        sh[tid] += t;
        __syncthreads();
    }
    if (tid < SCAN_NBLK) g_bsum[tid] = sh[tid] - v;
}

__global__ void k_scanC() {
    int i = blockIdx.x * blockDim.x + threadIdx.x;
    if (i < 2 * NN) {
        g_offs[i] += g_bsum[i / SCAN_ELEMS];
        int c = g_cnt[i];
        float inv = c > 0 ? 1.0f / (float)c : 0.0f;
        if (i < NN) g_dinv[i] = inv;
        else        g_binv[i - NN] = inv;
    }
    if (i == 0) g_offs[2 * NN] = 2 * NE;
}

// ---- CSR fill (decodes hei directly) ----
__global__ void k_fill(const void* __restrict__ hei) {
    int i = blockIdx.x * blockDim.x + threadIdx.x;
    if (i >= NE) return;
    bool i32 = (g_is_i32 != 0);
    int n, e;
    decode(hei, i32, i, n, e);
    int pn = g_offs[n] + atomicSub(&g_cnt[n], 1) - 1;
    g_csr[pn] = e;
    int pe = g_offs[NN + e] + atomicSub(&g_cnt[NN + e], 1) - 1;
    g_csr[pe] = n;
}

// ---- fp32 -> fp16 convert (vectorized) ----
__global__ void k_f2h(const float* __restrict__ src, __half* __restrict__ dst, int n4) {
    int i = blockIdx.x * blockDim.x + threadIdx.x;
    if (i < n4) {
        float4 v = ((const float4*)src)[i];
        __half2 h0 = __floats2half2_rn(v.x, v.y);
        __half2 h1 = __floats2half2_rn(v.z, v.w);
        uint2 o;
        o.x = *(u32*)&h0;
        o.y = *(u32*)&h1;
        ((uint2*)dst)[i] = o;
    }
}

// ---- tensor-core GEMM: C[M,128](fp16) = A[M,128](fp16) @ W[128,128](fp16), fp32 accum ----
__global__ __launch_bounds__(256) void k_gemm_mma(const __half* __restrict__ A,
                                                  const __half* __restrict__ Wh,
                                                  __half* __restrict__ C, int M) {
    extern __shared__ __half smem[];
    __half* sA = smem;                   // [128][ASTRIDE]
    __half* sB = smem + 128 * ASTRIDE;   // [128][ASTRIDE]  (k rows, n cols)
    int tid = threadIdx.x;
    int rb = blockIdx.x * 128;

    // load A tile (zeros past M)
#pragma unroll
    for (int it = 0; it < 8; it++) {
        int idx = (it * 256 + tid) * 8;
        int r = idx >> 7, c = idx & 127;
        uint4 v = make_uint4(0, 0, 0, 0);
        if (rb + r < M) v = *(const uint4*)(A + (size_t)(rb + r) * HID + c);
        *(uint4*)(sA + r * ASTRIDE + c) = v;
    }
    // load B tile (full W)
#pragma unroll
    for (int it = 0; it < 8; it++) {
        int idx = (it * 256 + tid) * 8;
        int r = idx >> 7, c = idx & 127;
        *(uint4*)(sB + r * ASTRIDE + c) = *(const uint4*)(Wh + r * HID + c);
    }
    __syncthreads();

    int w = tid >> 5, lane = tid & 31;
    int wm = (w & 3) * 32;   // warp M offset
    int wn = (w >> 2) * 64;  // warp N offset
    int lrow = (lane & 7) + ((lane >> 3) & 1) * 8;  // ldmatrix row within 16
    int lcol8 = (lane >> 4) * 8;                     // ldmatrix col half (0/8)

    float acc[2][8][4];
#pragma unroll
    for (int mi = 0; mi < 2; mi++)
#pragma unroll
        for (int nj = 0; nj < 8; nj++)
#pragma unroll
            for (int q = 0; q < 4; q++) acc[mi][nj][q] = 0.f;

#pragma unroll
    for (int ks = 0; ks < 8; ks++) {
        int k0 = ks * 16;
        u32 a[2][4];
#pragma unroll
        for (int mi = 0; mi < 2; mi++) {
            u32 ad = sptr(sA + (wm + mi * 16 + lrow) * ASTRIDE + k0 + lcol8);
            ldsm4(a[mi][0], a[mi][1], a[mi][2], a[mi][3], ad);
        }
        u32 b[8][2];
#pragma unroll
        for (int nj = 0; nj < 4; nj++) {
            u32 ad = sptr(sB + (k0 + lrow) * ASTRIDE + wn + nj * 16 + lcol8);
            u32 r0, r1, r2, r3;
            ldsm4t(r0, r1, r2, r3, ad);
            b[nj * 2][0] = r0; b[nj * 2][1] = r1;
            b[nj * 2 + 1][0] = r2; b[nj * 2 + 1][1] = r3;
        }
#pragma unroll
        for (int mi = 0; mi < 2; mi++)
#pragma unroll
            for (int nj = 0; nj < 8; nj++)
                mma16816(acc[mi][nj], a[mi], b[nj]);
    }

    // epilogue: fp32 -> fp16 stores
    int g = lane >> 2, t4 = lane & 3;
#pragma unroll
    for (int mi = 0; mi < 2; mi++) {
        int r0 = rb + wm + mi * 16 + g;
        int r1 = r0 + 8;
#pragma unroll
        for (int nj = 0; nj < 8; nj++) {
            int col = wn + nj * 8 + t4 * 2;
            if (r0 < M) {
                __half2 h = __floats2half2_rn(acc[mi][nj][0], acc[mi][nj][1]);
                *(__half2*)(C + (size_t)r0 * HID + col) = h;
            }
            if (r1 < M) {
                __half2 h = __floats2half2_rn(acc[mi][nj][2], acc[mi][nj][3]);
                *(__half2*)(C + (size_t)r1 * HID + col) = h;
            }
        }
    }
}

// ---- edge gather (fp16 in / fp16 out): m[e] = binv[e] * sum xw[n] ----
__global__ __launch_bounds__(256) void k_gather_e(const __half* __restrict__ src,
                                                  __half* __restrict__ dst) {
    int g = blockIdx.x * blockDim.x + threadIdx.x;
    int e = g >> 5;
    int lane = g & 31;
    if (e >= NN) return;
    int beg = g_offs[NN + e];
    int end = g_offs[NN + e + 1];
    float4 acc = make_float4(0.f, 0.f, 0.f, 0.f);
    const uint2* s2 = (const uint2*)src;
    int j = beg;
    for (; j + 1 < end; j += 2) {
        int n0 = g_csr[j];
        int n1 = g_csr[j + 1];
        uint2 u0 = s2[(size_t)n0 * 32 + lane];
        uint2 u1 = s2[(size_t)n1 * 32 + lane];
        float2 a0 = __half22float2(*(const __half2*)&u0.x);
        float2 a1 = __half22float2(*(const __half2*)&u0.y);
        float2 b0 = __half22float2(*(const __half2*)&u1.x);
        float2 b1 = __half22float2(*(const __half2*)&u1.y);
        acc.x += a0.x + b0.x;
        acc.y += a0.y + b0.y;
        acc.z += a1.x + b1.x;
        acc.w += a1.y + b1.y;
    }
    if (j < end) {
        int n0 = g_csr[j];
        uint2 u0 = s2[(size_t)n0 * 32 + lane];
        float2 a0 = __half22float2(*(const __half2*)&u0.x);
        float2 a1 = __half22float2(*(const __half2*)&u0.y);
        acc.x += a0.x; acc.y += a0.y; acc.z += a1.x; acc.w += a1.y;
    }
    float s = g_binv[e];
    __half2 o0 = __floats2half2_rn(acc.x * s, acc.y * s);
    __half2 o1 = __floats2half2_rn(acc.z * s, acc.w * s);
    uint2 ov;
    ov.x = *(const u32*)&o0;
    ov.y = *(const u32*)&o1;
    ((uint2*)dst)[(size_t)e * 32 + lane] = ov;
}

// ---- node gather: layer1 -> fp16 h; layer2 -> fp32 out with residual ----
template <bool RES, typename OUT>
__global__ __launch_bounds__(256) void k_gather_n(const __half* __restrict__ src,
                                                  const float* __restrict__ bias,
                                                  const float* __restrict__ pa,
                                                  const float* __restrict__ xres,
                                                  OUT* __restrict__ dst) {
    int g = blockIdx.x * blockDim.x + threadIdx.x;
    int n = g >> 5;
    int lane = g & 31;
    if (n >= NN) return;
    int beg = g_offs[n];
    int end = g_offs[n + 1];
    float4 acc = make_float4(0.f, 0.f, 0.f, 0.f);
    const uint2* s2 = (const uint2*)src;
    int j = beg;
    for (; j + 1 < end; j += 2) {
        int e0 = g_csr[j];
        int e1 = g_csr[j + 1];
        uint2 u0 = s2[(size_t)e0 * 32 + lane];
        uint2 u1 = s2[(size_t)e1 * 32 + lane];
        float2 a0 = __half22float2(*(const __half2*)&u0.x);
        float2 a1 = __half22float2(*(const __half2*)&u0.y);
        float2 b0 = __half22float2(*(const __half2*)&u1.x);
        float2 b1 = __half22float2(*(const __half2*)&u1.y);
        acc.x += a0.x + b0.x;
        acc.y += a0.y + b0.y;
        acc.z += a1.x + b1.x;
        acc.w += a1.y + b1.y;
    }
    if (j < end) {
        int e0 = g_csr[j];
        uint2 u0 = s2[(size_t)e0 * 32 + lane];
        float2 a0 = __half22float2(*(const __half2*)&u0.x);
        float2 a1 = __half22float2(*(const __half2*)&u0.y);
        acc.x += a0.x; acc.y += a0.y; acc.z += a1.x; acc.w += a1.y;
    }
    float d = g_dinv[n];
    float a = pa[0];
    float4 b = ((const float4*)bias)[lane];
    acc.x = acc.x * d + b.x;
    acc.y = acc.y * d + b.y;
    acc.z = acc.z * d + b.z;
    acc.w = acc.w * d + b.w;
    if (RES) {
        float4 xv = ((const float4*)xres)[(size_t)n * 32 + lane];
        acc.x += xv.x; acc.y += xv.y; acc.z += xv.z; acc.w += xv.w;
    }
    acc.x = acc.x >= 0.f ? acc.x : a * acc.x;
    acc.y = acc.y >= 0.f ? acc.y : a * acc.y;
    acc.z = acc.z >= 0.f ? acc.z : a * acc.z;
    acc.w = acc.w >= 0.f ? acc.w : a * acc.w;
    if (sizeof(OUT) == 2) {
        __half2 o0 = __floats2half2_rn(acc.x, acc.y);
        __half2 o1 = __floats2half2_rn(acc.z, acc.w);
        uint2 ov;
        ov.x = *(const u32*)&o0;
        ov.y = *(const u32*)&o1;
        ((uint2*)dst)[(size_t)n * 32 + lane] = ov;
    } else {
        ((float4*)dst)[(size_t)n * 32 + lane] = acc;
    }
}

extern "C" void kernel_launch(void* const* d_in, const int* in_sizes, int n_in,
                              void* d_out, int out_size) {
    (void)in_sizes; (void)n_in; (void)out_size;
    const float* x   = (const float*)d_in[0];
    const void*  hei = d_in[1];
    const float* W1  = (const float*)d_in[2];
    const float* b1  = (const float*)d_in[3];
    const float* W2  = (const float*)d_in[4];
    const float* b2  = (const float*)d_in[5];
    const float* pa  = (const float*)d_in[6];
    float* out = (float*)d_out;

    __half *pxh, *pw1h, *pw2h, *pxw, *pm, *ph;
    cudaGetSymbolAddress((void**)&pxh,  g_xh);
    cudaGetSymbolAddress((void**)&pw1h, g_w1h);
    cudaGetSymbolAddress((void**)&pw2h, g_w2h);
    cudaGetSymbolAddress((void**)&pxw,  g_xw);
    cudaGetSymbolAddress((void**)&pm,   g_m);
    cudaGetSymbolAddress((void**)&ph,   g_h);

    const int GW_BLOCKS = (NN * 32) / 256;
    const int GEMM_SMEM = 2 * 128 * ASTRIDE * 2;  // 69632 B
    static bool attr_set = false;
    if (!attr_set) {
        cudaFuncSetAttribute(k_gemm_mma, cudaFuncAttributeMaxDynamicSharedMemorySize, GEMM_SMEM);
        attr_set = true;
    }

    // fork: conversions + GEMM1 (side stream) || CSR prep (stream 0)
    cudaEventRecord(g_ss.evStart, 0);
    cudaStreamWaitEvent(g_ss.s, g_ss.evStart, 0);

    // prep on stream 0
    k_zero<<<(2 * NN + 255) / 256, 256>>>();
    k_detect<<<16, 256>>>((const long long*)hei);
    k_deg<<<(NE / 2 + 255) / 256, 256>>>(hei);
    k_scanA<<<SCAN_NBLK, SCAN_BS>>>();
    k_scanB<<<1, 64>>>();
    k_scanC<<<(2 * NN + 255) / 256, 256>>>();
    k_fill<<<(NE + 255) / 256, 256>>>(hei);

    // side stream: fp16 conversions + GEMM1
    k_f2h<<<(NN * HID / 4 + 255) / 256, 256, 0, g_ss.s>>>(x, pxh, NN * HID / 4);
    k_f2h<<<(HID * HID / 4 + 255) / 256, 256, 0, g_ss.s>>>(W1, pw1h, HID * HID / 4);
    k_f2h<<<(HID * HID / 4 + 255) / 256, 256, 0, g_ss.s>>>(W2, pw2h, HID * HID / 4);
    k_gemm_mma<<<(NN + 127) / 128, 256, GEMM_SMEM, g_ss.s>>>(pxh, pw1h, pxw, NN);
    cudaEventRecord(g_ss.evGemm, g_ss.s);
    cudaStreamWaitEvent(0, g_ss.evGemm, 0);

    // ---- layer 1 aggregation ----
    k_gather_e<<<GW_BLOCKS, 256>>>(pxw, pm);
    k_gather_n<false, __half><<<GW_BLOCKS, 256>>>(pm, b1, pa, nullptr, ph);

    // ---- layer 2 ----
    k_gemm_mma<<<(NN + 127) / 128, 256, GEMM_SMEM>>>(ph, pw2h, pxw, NN);
    k_gather_e<<<GW_BLOCKS, 256>>>(pxw, pm);
    k_gather_n<true, float><<<GW_BLOCKS, 256>>>(pm, b2, pa, x, out);
}

// round 9
// speedup vs baseline: 2.6832x; 1.0332x over previous
#include <cuda_runtime.h>
#include <cuda_fp16.h>

#define NN 50000
#define NE 600000
#define HID 128

#define SCAN_BS 256
#define SCAN_VT 8
#define SCAN_ELEMS (SCAN_BS * SCAN_VT)              // 2048
#define SCAN_NBLK ((2 * NN + SCAN_ELEMS - 1) / SCAN_ELEMS)  // 49

#define ASTRIDE 136  // smem row stride in halfs

typedef unsigned long long u64;
typedef unsigned int u32;

// ---- scratch ----
__device__ int    g_cnt[2 * NN];
__device__ int    g_offs[2 * NN + 1];
__device__ int    g_bsum[64];
__device__ int    g_csr[2 * NE];
__device__ float  g_dinv[NN];
__device__ float  g_binv[NN];
__device__ __half g_xh[NN * HID];
__device__ __half g_w1h[HID * HID];
__device__ __half g_w2h[HID * HID];
__device__ __half g_xw[NN * HID];
__device__ __half g_m[NN * HID];
__device__ __half g_h[NN * HID];
__device__ int    g_is_i32;

// ---- side stream + events ----
struct SideStream {
    cudaStream_t s;
    cudaEvent_t evStart, evGemm, evScan, evFillN;
    SideStream() {
        cudaStreamCreateWithFlags(&s, cudaStreamNonBlocking);
        cudaEventCreateWithFlags(&evStart, cudaEventDisableTiming);
        cudaEventCreateWithFlags(&evGemm, cudaEventDisableTiming);
        cudaEventCreateWithFlags(&evScan, cudaEventDisableTiming);
        cudaEventCreateWithFlags(&evFillN, cudaEventDisableTiming);
    }
};
static SideStream g_ss;

// ---- PTX helpers ----
__device__ __forceinline__ u32 sptr(const void* p) {
    return (u32)__cvta_generic_to_shared(p);
}
__device__ __forceinline__ void ldsm4(u32& r0, u32& r1, u32& r2, u32& r3, u32 a) {
    asm volatile("ldmatrix.sync.aligned.m8n8.x4.shared.b16 {%0,%1,%2,%3},[%4];"
                 : "=r"(r0), "=r"(r1), "=r"(r2), "=r"(r3) : "r"(a));
}
__device__ __forceinline__ void ldsm4t(u32& r0, u32& r1, u32& r2, u32& r3, u32 a) {
    asm volatile("ldmatrix.sync.aligned.m8n8.x4.trans.shared.b16 {%0,%1,%2,%3},[%4];"
                 : "=r"(r0), "=r"(r1), "=r"(r2), "=r"(r3) : "r"(a));
}
__device__ __forceinline__ void mma16816(float* d, const u32* a, const u32* b) {
    asm volatile("mma.sync.aligned.m16n8k16.row.col.f32.f16.f16.f32 "
                 "{%0,%1,%2,%3},{%4,%5,%6,%7},{%8,%9},{%0,%1,%2,%3};"
                 : "+f"(d[0]), "+f"(d[1]), "+f"(d[2]), "+f"(d[3])
                 : "r"(a[0]), "r"(a[1]), "r"(a[2]), "r"(a[3]), "r"(b[0]), "r"(b[1]));
}

// ---- zero counts ----
__global__ void k_zero() {
    int i = blockIdx.x * blockDim.x + threadIdx.x;
    if (i < 2 * NN) g_cnt[i] = 0;
}

// ---- dtype detect: one block, ballot, single definitive write ----
__global__ void k_detect(const long long* __restrict__ hei64) {
    int tid = threadIdx.x;
    int bad = 0;
#pragma unroll
    for (int t = 0; t < 4; t++) {
        long long v = hei64[tid + t * 1024];
        if (v < 0 || v >= NN) bad = 1;
    }
    __shared__ int sbad[32];
    unsigned wb = __ballot_sync(0xffffffffu, bad);
    if ((tid & 31) == 0) sbad[tid >> 5] = (wb != 0);
    __syncthreads();
    if (tid == 0) {
        int any = 0;
        for (int w = 0; w < 32; w++) any |= sbad[w];
        g_is_i32 = any;
    }
}

__device__ __forceinline__ void decode(const void* hei, bool i32, int i, int& n, int& e) {
    if (i32) {
        n = ((const int*)hei)[i];
        e = ((const int*)hei)[NE + i];
    } else {
        n = (int)((const long long*)hei)[i];
        e = (int)((const long long*)hei)[NE + i];
    }
    if (n < 0 || n >= NN) n = 0;
    if (e < 0 || e >= NN) e = 0;
}

// ---- degree counts ----
__global__ void k_deg(const void* __restrict__ hei) {
    int t = blockIdx.x * blockDim.x + threadIdx.x;
    int i0 = t * 2;
    if (i0 >= NE) return;
    bool i32 = (g_is_i32 != 0);
#pragma unroll
    for (int k = 0; k < 2; k++) {
        int i = i0 + k;
        if (i >= NE) break;
        int n, e;
        decode(hei, i32, i, n, e);
        atomicAdd(&g_cnt[n], 1);
        atomicAdd(&g_cnt[NN + e], 1);
    }
}

// ---- scan pass A: per-block scan + block sums ----
__global__ __launch_bounds__(SCAN_BS) void k_scanA() {
    __shared__ int s[SCAN_BS];
    int blk = blockIdx.x, tid = threadIdx.x;
    int base = blk * SCAN_ELEMS + tid * SCAN_VT;
    int v[SCAN_VT];
    int sum = 0;
#pragma unroll
    for (int t = 0; t < SCAN_VT; t++) {
        v[t] = (base + t < 2 * NN) ? g_cnt[base + t] : 0;
        sum += v[t];
    }
    s[tid] = sum;
    __syncthreads();
    for (int off = 1; off < SCAN_BS; off <<= 1) {
        int t = (tid >= off) ? s[tid - off] : 0;
        __syncthreads();
        s[tid] += t;
        __syncthreads();
    }
    if (tid == SCAN_BS - 1) g_bsum[blk] = s[tid];
    int run = s[tid] - sum;
#pragma unroll
    for (int t = 0; t < SCAN_VT; t++) {
        if (base + t < 2 * NN) g_offs[base + t] = run;
        run += v[t];
    }
}

// ---- scan pass C (fused block-sum scan) + inverse degrees ----
__global__ void k_scanC() {
    __shared__ int sh[64];
    int tid = threadIdx.x;
    if (tid < 64) {
        // shifted load -> inclusive scan yields exclusive block prefix
        sh[tid] = (tid > 0 && tid - 1 < SCAN_NBLK) ? g_bsum[tid - 1] : 0;
    }
    __syncthreads();
    for (int off = 1; off < 64; off <<= 1) {
        int t = 0;
        if (tid < 64 && tid >= off) t = sh[tid - off];
        __syncthreads();
        if (tid < 64) sh[tid] += t;
        __syncthreads();
    }
    int i = blockIdx.x * blockDim.x + tid;
    if (i < 2 * NN) {
        g_offs[i] += sh[i / SCAN_ELEMS];
        int c = g_cnt[i];
        float inv = c > 0 ? 1.0f / (float)c : 0.0f;
        if (i < NN) g_dinv[i] = inv;
        else        g_binv[i - NN] = inv;
    }
    if (i == 0) g_offs[2 * NN] = 2 * NE;
}

// ---- CSR fill, split: edge rows / node rows ----
__global__ void k_fill_e(const void* __restrict__ hei) {
    int i = blockIdx.x * blockDim.x + threadIdx.x;
    if (i >= NE) return;
    bool i32 = (g_is_i32 != 0);
    int n, e;
    decode(hei, i32, i, n, e);
    int pe = g_offs[NN + e] + atomicSub(&g_cnt[NN + e], 1) - 1;
    g_csr[pe] = n;
}

__global__ void k_fill_n(const void* __restrict__ hei) {
    int i = blockIdx.x * blockDim.x + threadIdx.x;
    if (i >= NE) return;
    bool i32 = (g_is_i32 != 0);
    int n, e;
    decode(hei, i32, i, n, e);
    int pn = g_offs[n] + atomicSub(&g_cnt[n], 1) - 1;
    g_csr[pn] = e;
}

// ---- fp32 -> fp16 convert ----
__global__ void k_f2h(const float* __restrict__ src, __half* __restrict__ dst, int n4) {
    int i = blockIdx.x * blockDim.x + threadIdx.x;
    if (i < n4) {
        float4 v = ((const float4*)src)[i];
        __half2 h0 = __floats2half2_rn(v.x, v.y);
        __half2 h1 = __floats2half2_rn(v.z, v.w);
        uint2 o;
        o.x = *(u32*)&h0;
        o.y = *(u32*)&h1;
        ((uint2*)dst)[i] = o;
    }
}

// ---- tensor-core GEMM ----
__global__ __launch_bounds__(256) void k_gemm_mma(const __half* __restrict__ A,
                                                  const __half* __restrict__ Wh,
                                                  __half* __restrict__ C, int M) {
    extern __shared__ __half smem[];
    __half* sA = smem;
    __half* sB = smem + 128 * ASTRIDE;
    int tid = threadIdx.x;
    int rb = blockIdx.x * 128;

#pragma unroll
    for (int it = 0; it < 8; it++) {
        int idx = (it * 256 + tid) * 8;
        int r = idx >> 7, c = idx & 127;
        uint4 v = make_uint4(0, 0, 0, 0);
        if (rb + r < M) v = *(const uint4*)(A + (size_t)(rb + r) * HID + c);
        *(uint4*)(sA + r * ASTRIDE + c) = v;
    }
#pragma unroll
    for (int it = 0; it < 8; it++) {
        int idx = (it * 256 + tid) * 8;
        int r = idx >> 7, c = idx & 127;
        *(uint4*)(sB + r * ASTRIDE + c) = *(const uint4*)(Wh + r * HID + c);
    }
    __syncthreads();

    int w = tid >> 5, lane = tid & 31;
    int wm = (w & 3) * 32;
    int wn = (w >> 2) * 64;
    int lrow = (lane & 7) + ((lane >> 3) & 1) * 8;
    int lcol8 = (lane >> 4) * 8;

    float acc[2][8][4];
#pragma unroll
    for (int mi = 0; mi < 2; mi++)
#pragma unroll
        for (int nj = 0; nj < 8; nj++)
#pragma unroll
            for (int q = 0; q < 4; q++) acc[mi][nj][q] = 0.f;

#pragma unroll
    for (int ks = 0; ks < 8; ks++) {
        int k0 = ks * 16;
        u32 a[2][4];
#pragma unroll
        for (int mi = 0; mi < 2; mi++) {
            u32 ad = sptr(sA + (wm + mi * 16 + lrow) * ASTRIDE + k0 + lcol8);
            ldsm4(a[mi][0], a[mi][1], a[mi][2], a[mi][3], ad);
        }
        u32 b[8][2];
#pragma unroll
        for (int nj = 0; nj < 4; nj++) {
            u32 ad = sptr(sB + (k0 + lrow) * ASTRIDE + wn + nj * 16 + lcol8);
            u32 r0, r1, r2, r3;
            ldsm4t(r0, r1, r2, r3, ad);
            b[nj * 2][0] = r0; b[nj * 2][1] = r1;
            b[nj * 2 + 1][0] = r2; b[nj * 2 + 1][1] = r3;
        }
#pragma unroll
        for (int mi = 0; mi < 2; mi++)
#pragma unroll
            for (int nj = 0; nj < 8; nj++)
                mma16816(acc[mi][nj], a[mi], b[nj]);
    }

    int g = lane >> 2, t4 = lane & 3;
#pragma unroll
    for (int mi = 0; mi < 2; mi++) {
        int r0 = rb + wm + mi * 16 + g;
        int r1 = r0 + 8;
#pragma unroll
        for (int nj = 0; nj < 8; nj++) {
            int col = wn + nj * 8 + t4 * 2;
            if (r0 < M) {
                __half2 h = __floats2half2_rn(acc[mi][nj][0], acc[mi][nj][1]);
                *(__half2*)(C + (size_t)r0 * HID + col) = h;
            }
            if (r1 < M) {
                __half2 h = __floats2half2_rn(acc[mi][nj][2], acc[mi][nj][3]);
                *(__half2*)(C + (size_t)r1 * HID + col) = h;
            }
        }
    }
}

// ---- accumulate helper ----
__device__ __forceinline__ void acc_row(float4& acc, uint2 u) {
    float2 a0 = __half22float2(*(const __half2*)&u.x);
    float2 a1 = __half22float2(*(const __half2*)&u.y);
    acc.x += a0.x; acc.y += a0.y; acc.z += a1.x; acc.w += a1.y;
}

// ---- edge gather: m[e] = binv[e] * sum xw[n], 4-way unrolled ----
__global__ __launch_bounds__(256) void k_gather_e(const __half* __restrict__ src,
                                                  __half* __restrict__ dst) {
    int g = blockIdx.x * blockDim.x + threadIdx.x;
    int e = g >> 5;
    int lane = g & 31;
    if (e >= NN) return;
    int beg = g_offs[NN + e];
    int end = g_offs[NN + e + 1];
    float4 acc = make_float4(0.f, 0.f, 0.f, 0.f);
    const uint2* s2 = (const uint2*)src;
    int j = beg;
    for (; j + 3 < end; j += 4) {
        int i0 = g_csr[j], i1 = g_csr[j + 1], i2 = g_csr[j + 2], i3 = g_csr[j + 3];
        uint2 u0 = s2[(size_t)i0 * 32 + lane];
        uint2 u1 = s2[(size_t)i1 * 32 + lane];
        uint2 u2 = s2[(size_t)i2 * 32 + lane];
        uint2 u3 = s2[(size_t)i3 * 32 + lane];
        acc_row(acc, u0); acc_row(acc, u1); acc_row(acc, u2); acc_row(acc, u3);
    }
    for (; j < end; j++) {
        uint2 u0 = s2[(size_t)g_csr[j] * 32 + lane];
        acc_row(acc, u0);
    }
    float s = g_binv[e];
    __half2 o0 = __floats2half2_rn(acc.x * s, acc.y * s);
    __half2 o1 = __floats2half2_rn(acc.z * s, acc.w * s);
    uint2 ov;
    ov.x = *(const u32*)&o0;
    ov.y = *(const u32*)&o1;
    ((uint2*)dst)[(size_t)e * 32 + lane] = ov;
}

// ---- node gather, 4-way unrolled ----
template <bool RES, typename OUT>
__global__ __launch_bounds__(256) void k_gather_n(const __half* __restrict__ src,
                                                  const float* __restrict__ bias,
                                                  const float* __restrict__ pa,
                                                  const float* __restrict__ xres,
                                                  OUT* __restrict__ dst) {
    int g = blockIdx.x * blockDim.x + threadIdx.x;
    int n = g >> 5;
    int lane = g & 31;
    if (n >= NN) return;
    int beg = g_offs[n];
    int end = g_offs[n + 1];
    float4 acc = make_float4(0.f, 0.f, 0.f, 0.f);
    const uint2* s2 = (const uint2*)src;
    int j = beg;
    for (; j + 3 < end; j += 4) {
        int i0 = g_csr[j], i1 = g_csr[j + 1], i2 = g_csr[j + 2], i3 = g_csr[j + 3];
        uint2 u0 = s2[(size_t)i0 * 32 + lane];
        uint2 u1 = s2[(size_t)i1 * 32 + lane];
        uint2 u2 = s2[(size_t)i2 * 32 + lane];
        uint2 u3 = s2[(size_t)i3 * 32 + lane];
        acc_row(acc, u0); acc_row(acc, u1); acc_row(acc, u2); acc_row(acc, u3);
    }
    for (; j < end; j++) {
        uint2 u0 = s2[(size_t)g_csr[j] * 32 + lane];
        acc_row(acc, u0);
    }
    float d = g_dinv[n];
    float a = pa[0];
    float4 b = ((const float4*)bias)[lane];
    acc.x = acc.x * d + b.x;
    acc.y = acc.y * d + b.y;
    acc.z = acc.z * d + b.z;
    acc.w = acc.w * d + b.w;
    if (RES) {
        float4 xv = ((const float4*)xres)[(size_t)n * 32 + lane];
        acc.x += xv.x; acc.y += xv.y; acc.z += xv.z; acc.w += xv.w;
    }
    acc.x = acc.x >= 0.f ? acc.x : a * acc.x;
    acc.y = acc.y >= 0.f ? acc.y : a * acc.y;
    acc.z = acc.z >= 0.f ? acc.z : a * acc.z;
    acc.w = acc.w >= 0.f ? acc.w : a * acc.w;
    if (sizeof(OUT) == 2) {
        __half2 o0 = __floats2half2_rn(acc.x, acc.y);
        __half2 o1 = __floats2half2_rn(acc.z, acc.w);
        uint2 ov;
        ov.x = *(const u32*)&o0;
        ov.y = *(const u32*)&o1;
        ((uint2*)dst)[(size_t)n * 32 + lane] = ov;
    } else {
        ((float4*)dst)[(size_t)n * 32 + lane] = acc;
    }
}

extern "C" void kernel_launch(void* const* d_in, const int* in_sizes, int n_in,
                              void* d_out, int out_size) {
    (void)in_sizes; (void)n_in; (void)out_size;
    const float* x   = (const float*)d_in[0];
    const void*  hei = d_in[1];
    const float* W1  = (const float*)d_in[2];
    const float* b1  = (const float*)d_in[3];
    const float* W2  = (const float*)d_in[4];
    const float* b2  = (const float*)d_in[5];
    const float* pa  = (const float*)d_in[6];
    float* out = (float*)d_out;

    __half *pxh, *pw1h, *pw2h, *pxw, *pm, *ph;
    cudaGetSymbolAddress((void**)&pxh,  g_xh);
    cudaGetSymbolAddress((void**)&pw1h, g_w1h);
    cudaGetSymbolAddress((void**)&pw2h, g_w2h);
    cudaGetSymbolAddress((void**)&pxw,  g_xw);
    cudaGetSymbolAddress((void**)&pm,   g_m);
    cudaGetSymbolAddress((void**)&ph,   g_h);

    const int GW_BLOCKS = (NN * 32) / 256;
    const int GEMM_SMEM = 2 * 128 * ASTRIDE * 2;
    cudaFuncSetAttribute(k_gemm_mma, cudaFuncAttributeMaxDynamicSharedMemorySize, GEMM_SMEM);

    // fork
    cudaEventRecord(g_ss.evStart, 0);
    cudaStreamWaitEvent(g_ss.s, g_ss.evStart, 0);

    // stream 0: prep
    k_detect<<<1, 1024>>>((const long long*)hei);
    k_zero<<<(2 * NN + 255) / 256, 256>>>();
    k_deg<<<(NE / 2 + 255) / 256, 256>>>(hei);
    k_scanA<<<SCAN_NBLK, SCAN_BS>>>();
    k_scanC<<<(2 * NN + 255) / 256, 256>>>();
    cudaEventRecord(g_ss.evScan, 0);
    k_fill_e<<<(NE + 255) / 256, 256>>>(hei);

    // side stream: fp16 conversions + GEMM1, then node-CSR fill (after scan)
    k_f2h<<<(NN * HID / 4 + 255) / 256, 256, 0, g_ss.s>>>(x, pxh, NN * HID / 4);
    k_f2h<<<(HID * HID / 4 + 255) / 256, 256, 0, g_ss.s>>>(W1, pw1h, HID * HID / 4);
    k_f2h<<<(HID * HID / 4 + 255) / 256, 256, 0, g_ss.s>>>(W2, pw2h, HID * HID / 4);
    k_gemm_mma<<<(NN + 127) / 128, 256, GEMM_SMEM, g_ss.s>>>(pxh, pw1h, pxw, NN);
    cudaEventRecord(g_ss.evGemm, g_ss.s);
    cudaStreamWaitEvent(g_ss.s, g_ss.evScan, 0);
    k_fill_n<<<(NE + 255) / 256, 256, 0, g_ss.s>>>(hei);
    cudaEventRecord(g_ss.evFillN, g_ss.s);

    // layer 1 aggregation
    cudaStreamWaitEvent(0, g_ss.evGemm, 0);
    k_gather_e<<<GW_BLOCKS, 256>>>(pxw, pm);
    cudaStreamWaitEvent(0, g_ss.evFillN, 0);
    k_gather_n<false, __half><<<GW_BLOCKS, 256>>>(pm, b1, pa, nullptr, ph);

    // layer 2
    k_gemm_mma<<<(NN + 127) / 128, 256, GEMM_SMEM>>>(ph, pw2h, pxw, NN);
    k_gather_e<<<GW_BLOCKS, 256>>>(pxw, pm);
    k_gather_n<true, float><<<GW_BLOCKS, 256>>>(pm, b2, pa, x, out);
}